// round 15
// baseline (speedup 1.0000x reference)
#include <cuda_runtime.h>
#include <cuda_fp16.h>
#include <cstdint>

// MeanPooling == batched GEMM + row scale, all-fp16 mma.sync.
// CTA tile 128x128, 512 threads (16 warps, 4M x 4N), K-chunk 64.
// Register pipeline distance 2 + intra-chunk software pipelining:
//   LDSM frags double-buffered (prefetch ko+1 during MMA ko),
//   CVTSTS(c+1) after ko0, LDG(c+2) after ko2 (fills MMA shadow).
//   d_in[0] doc_state      [B=32, L=2048, D=256] fp32   (B operand)
//   d_in[1] entity_mapping [B=32, E=256,  L=2048] fp32  (A operand)
//   d_in[2] entity_lens    [B=32, E=256] fp32
// Output [B, E, D] fp32 = (emap @ doc) / lens

#define BATCH 32
#define E_DIM 256
#define L_DIM 2048
#define D_DIM 256

#define TILE_M 128
#define TILE_N 128
#define CHUNK 64
#define NCHUNK (L_DIM / CHUNK)      // 32
#define NTHREADS 512

// fp16 tiles: strides == 16 mod 128 -> conflict-free ldmatrix row phases.
#define A_STRIDE_B 144                     // 64 halfs + 8 pad
#define B_STRIDE_B 272                     // 128 halfs + 8 pad
#define A16_BYTES (TILE_M * A_STRIDE_B)    // 18432
#define B16_BYTES (CHUNK * B_STRIDE_B)     // 17408
#define F16_STAGE (A16_BYTES + B16_BYTES)  // 35840
#define SMEM_TOTAL (2 * F16_STAGE)         // 71680

static __device__ __forceinline__ uint32_t smem_u32(const void* p) {
    uint32_t a;
    asm("{ .reg .u64 t; cvta.to.shared.u64 t, %1; cvt.u32.u64 %0, t; }"
        : "=r"(a) : "l"(p));
    return a;
}

#define LDSM_X4(r0, r1, r2, r3, addr) \
    asm volatile("ldmatrix.sync.aligned.m8n8.x4.shared.b16 {%0,%1,%2,%3}, [%4];" \
                 : "=r"(r0), "=r"(r1), "=r"(r2), "=r"(r3) : "r"(addr))

#define LDSM_X4_T(r0, r1, r2, r3, addr) \
    asm volatile("ldmatrix.sync.aligned.m8n8.x4.trans.shared.b16 {%0,%1,%2,%3}, [%4];" \
                 : "=r"(r0), "=r"(r1), "=r"(r2), "=r"(r3) : "r"(addr))

#define MMA16816(d, a0, a1, a2, a3, b0, b1) \
    asm volatile("mma.sync.aligned.m16n8k16.row.col.f32.f16.f16.f32 " \
                 "{%0,%1,%2,%3}, {%4,%5,%6,%7}, {%8,%9}, {%0,%1,%2,%3};" \
                 : "+f"((d)[0]), "+f"((d)[1]), "+f"((d)[2]), "+f"((d)[3]) \
                 : "r"(a0), "r"(a1), "r"(a2), "r"(a3), "r"(b0), "r"(b1))

static __device__ __forceinline__ uint32_t cvt2(float x, float y)
{
    uint32_t r;
    asm("cvt.rn.f16x2.f32 %0, %1, %2;" : "=r"(r) : "f"(y), "f"(x));
    return r;
}

__global__ void __launch_bounds__(NTHREADS, 1)
mean_pool_hmma(const float* __restrict__ doc,
               const float* __restrict__ emap,
               const float* __restrict__ lens,
               float* __restrict__ out)
{
    extern __shared__ char smem[];
    const uint32_t sbase = smem_u32(smem);

    const int tid = threadIdx.x;
    const int wid = tid >> 5;
    const int lid = tid & 31;
    const int wm  = wid & 3;        // 4 warps in M (32 rows each)
    const int wn  = wid >> 2;       // 4 warps in N (32 cols each)

    const int b     = blockIdx.z;
    const int tileM = blockIdx.y * TILE_M;
    const int tileN = blockIdx.x * TILE_N;

    const float* A  = emap + (size_t)b * E_DIM * L_DIM + (size_t)tileM * L_DIM;
    const float* Bm = doc  + (size_t)b * L_DIM * D_DIM + tileN;
    float*       C  = out  + (size_t)b * E_DIM * D_DIM;

    float acc[2][4][4] = {};            // [m16-tile][n8-tile][frag]

    float4 araw[4];
    float4 braw[4];

    // MMA operand fragments, double-buffered across ko steps
    uint32_t afr[2][2][4];              // [parity][mi][reg]
    uint32_t bfr[2][2][4];              // [parity][nt][reg]

    // ldmatrix lane addressing
    const uint32_t a_lrow = (uint32_t)(wm * 32 + (lid & 15));
    const uint32_t a_lcol = (uint32_t)((lid >> 4) * 16);              // bytes
    const uint32_t b_lrow = (uint32_t)(lid & 15);
    const uint32_t b_lcol = (uint32_t)(wn * 64 + (lid >> 4) * 16);    // bytes

    #define LDG_CHUNK(k0) do {                                                 \
        _Pragma("unroll")                                                      \
        for (int i = 0; i < 4; i++) {                                          \
            const int u = tid + 512 * i;                                       \
            araw[i] = *reinterpret_cast<const float4*>(                        \
                &A[(size_t)(u >> 4) * L_DIM + (k0) + (u & 15) * 4]);           \
        }                                                                      \
        _Pragma("unroll")                                                      \
        for (int i = 0; i < 4; i++) {                                          \
            const int u = tid + 512 * i;                                       \
            braw[i] = *reinterpret_cast<const float4*>(                        \
                &Bm[(size_t)((k0) + (u >> 5)) * D_DIM + (u & 31) * 4]);        \
        }                                                                      \
    } while (0)

    #define CVTSTS_CHUNK(buf) do {                                             \
        char* dstA = smem + (buf) * F16_STAGE;                                 \
        char* dstB = dstA + A16_BYTES;                                         \
        _Pragma("unroll")                                                      \
        for (int i = 0; i < 4; i++) {                                          \
            const int u = tid + 512 * i;                                       \
            float4 v = araw[i];                                                \
            *reinterpret_cast<uint2*>(dstA + (u >> 4) * A_STRIDE_B             \
                                      + (u & 15) * 8)                          \
                = make_uint2(cvt2(v.x, v.y), cvt2(v.z, v.w));                  \
        }                                                                      \
        _Pragma("unroll")                                                      \
        for (int i = 0; i < 4; i++) {                                          \
            const int u = tid + 512 * i;                                       \
            float4 v = braw[i];                                                \
            *reinterpret_cast<uint2*>(dstB + (u >> 5) * B_STRIDE_B             \
                                      + (u & 31) * 8)                          \
                = make_uint2(cvt2(v.x, v.y), cvt2(v.z, v.w));                  \
        }                                                                      \
    } while (0)

    #define LDSM_FRAGS(p, aT, bT, ko) do {                                     \
        const uint32_t akb = a_lcol + (uint32_t)((ko) * 32);                   \
        _Pragma("unroll")                                                      \
        for (int mi = 0; mi < 2; mi++) {                                       \
            const uint32_t ao = (a_lrow + mi * 16) * A_STRIDE_B + akb;         \
            LDSM_X4(afr[p][mi][0], afr[p][mi][1], afr[p][mi][2],               \
                    afr[p][mi][3], (aT) + ao);                                 \
        }                                                                      \
        _Pragma("unroll")                                                      \
        for (int nt = 0; nt < 2; nt++) {                                       \
            const uint32_t bo = (b_lrow + (uint32_t)((ko) * 16)) * B_STRIDE_B  \
                                + b_lcol + (uint32_t)(nt * 32);                \
            LDSM_X4_T(bfr[p][nt][0], bfr[p][nt][1], bfr[p][nt][2],             \
                      bfr[p][nt][3], (bT) + bo);                               \
        }                                                                      \
    } while (0)

    #define MMA_FRAGS(p) do {                                                  \
        _Pragma("unroll")                                                      \
        for (int nt = 0; nt < 2; nt++) {                                       \
            _Pragma("unroll")                                                  \
            for (int mi = 0; mi < 2; mi++) {                                   \
                MMA16816(acc[mi][nt * 2],                                      \
                         afr[p][mi][0], afr[p][mi][1], afr[p][mi][2],          \
                         afr[p][mi][3], bfr[p][nt][0], bfr[p][nt][1]);         \
                MMA16816(acc[mi][nt * 2 + 1],                                  \
                         afr[p][mi][0], afr[p][mi][1], afr[p][mi][2],          \
                         afr[p][mi][3], bfr[p][nt][2], bfr[p][nt][3]);         \
            }                                                                  \
        }                                                                      \
    } while (0)

    // ---- prologue ----
    LDG_CHUNK(0);
    CVTSTS_CHUNK(0);             // stalls on DRAM once
    LDG_CHUNK(CHUNK);            // chunk 1 in flight (full iter of slack)
    __syncthreads();

    for (int c = 0; c < NCHUNK; c++) {
        const uint32_t f16 = sbase + (uint32_t)((c & 1) * F16_STAGE);
        const uint32_t aT  = f16;
        const uint32_t bT  = f16 + A16_BYTES;

        // prefetch ko=0 fragments
        LDSM_FRAGS(0, aT, bT, 0);

        #pragma unroll
        for (int ko = 0; ko < 4; ko++) {
            const int p = ko & 1;
            if (ko < 3)
                LDSM_FRAGS(p ^ 1, aT, bT, ko + 1);   // prefetch next frags
            MMA_FRAGS(p);
            if (ko == 0 && c + 1 < NCHUNK)
                CVTSTS_CHUNK((c + 1) & 1);           // fills MMA shadow
            if (ko == 2 && c + 2 < NCHUNK)
                LDG_CHUNK((c + 2) * CHUNK);          // after raws consumed
        }

        // orders STS(c+1) before compute(c+1); compute(c) before STS(c+2)
        __syncthreads();
    }

    // ---- epilogue: scale by 1/len, store ----
    #pragma unroll
    for (int mi = 0; mi < 2; mi++) {
        const int r0 = tileM + wm * 32 + mi * 16 + (lid >> 2);
        const int r1 = r0 + 8;
        const float inv0 = 1.0f / lens[(size_t)b * E_DIM + r0];
        const float inv1 = 1.0f / lens[(size_t)b * E_DIM + r1];
        #pragma unroll
        for (int j = 0; j < 4; j++) {
            const int col = tileN + wn * 32 + j * 8 + (lid & 3) * 2;
            float2 o0 = make_float2(acc[mi][j][0] * inv0, acc[mi][j][1] * inv0);
            float2 o1 = make_float2(acc[mi][j][2] * inv1, acc[mi][j][3] * inv1);
            *reinterpret_cast<float2*>(&C[(size_t)r0 * D_DIM + col]) = o0;
            *reinterpret_cast<float2*>(&C[(size_t)r1 * D_DIM + col]) = o1;
        }
    }
}

extern "C" void kernel_launch(void* const* d_in, const int* in_sizes, int n_in,
                              void* d_out, int out_size)
{
    const float* doc  = (const float*)d_in[0];
    const float* emap = (const float*)d_in[1];
    const float* lens = (const float*)d_in[2];
    float* out = (float*)d_out;

    cudaFuncSetAttribute(mean_pool_hmma,
                         cudaFuncAttributeMaxDynamicSharedMemorySize, SMEM_TOTAL);

    dim3 grid(D_DIM / TILE_N, E_DIM / TILE_M, BATCH);   // (2, 2, 32) = 128 CTAs
    mean_pool_hmma<<<grid, NTHREADS, SMEM_TOTAL>>>(doc, emap, lens, out);
}

// round 16
// speedup vs baseline: 1.0409x; 1.0409x over previous
#include <cuda_runtime.h>
#include <cuda_fp16.h>
#include <cstdint>

// MeanPooling == batched GEMM + row scale, all-fp16 mma.sync.
// CTA tile 128x128, 512 threads (16 warps, 4M x 4N), K-chunk 64.
// 4-stage fp16 ring, __syncthreads every 2 chunks (16 barriers total):
//   iter c: compute(c) [buf c%4] | CVTSTS(c+2 -> buf (c+2)%4) | LDG(c+3)
//   barrier at end of odd iters only; write->read separated by >=1 barrier,
//   buffer reuse separated by >=2 barriers (drift window = 1 chunk).
//   d_in[0] doc_state      [B=32, L=2048, D=256] fp32   (B operand)
//   d_in[1] entity_mapping [B=32, E=256,  L=2048] fp32  (A operand)
//   d_in[2] entity_lens    [B=32, E=256] fp32
// Output [B, E, D] fp32 = (emap @ doc) / lens

#define BATCH 32
#define E_DIM 256
#define L_DIM 2048
#define D_DIM 256

#define TILE_M 128
#define TILE_N 128
#define CHUNK 64
#define NCHUNK (L_DIM / CHUNK)      // 32
#define NTHREADS 512

// fp16 tiles: strides == 16 mod 128 -> conflict-free ldmatrix row phases.
#define A_STRIDE_B 144                     // 64 halfs + 8 pad
#define B_STRIDE_B 272                     // 128 halfs + 8 pad
#define A16_BYTES (TILE_M * A_STRIDE_B)    // 18432
#define B16_BYTES (CHUNK * B_STRIDE_B)     // 17408
#define F16_STAGE (A16_BYTES + B16_BYTES)  // 35840
#define NSTAGE 4
#define SMEM_TOTAL (NSTAGE * F16_STAGE)    // 143360

static __device__ __forceinline__ uint32_t smem_u32(const void* p) {
    uint32_t a;
    asm("{ .reg .u64 t; cvta.to.shared.u64 t, %1; cvt.u32.u64 %0, t; }"
        : "=r"(a) : "l"(p));
    return a;
}

#define LDSM_X4(r0, r1, r2, r3, addr) \
    asm volatile("ldmatrix.sync.aligned.m8n8.x4.shared.b16 {%0,%1,%2,%3}, [%4];" \
                 : "=r"(r0), "=r"(r1), "=r"(r2), "=r"(r3) : "r"(addr))

#define LDSM_X4_T(r0, r1, r2, r3, addr) \
    asm volatile("ldmatrix.sync.aligned.m8n8.x4.trans.shared.b16 {%0,%1,%2,%3}, [%4];" \
                 : "=r"(r0), "=r"(r1), "=r"(r2), "=r"(r3) : "r"(addr))

#define MMA16816(d, a0, a1, a2, a3, b0, b1) \
    asm volatile("mma.sync.aligned.m16n8k16.row.col.f32.f16.f16.f32 " \
                 "{%0,%1,%2,%3}, {%4,%5,%6,%7}, {%8,%9}, {%0,%1,%2,%3};" \
                 : "+f"((d)[0]), "+f"((d)[1]), "+f"((d)[2]), "+f"((d)[3]) \
                 : "r"(a0), "r"(a1), "r"(a2), "r"(a3), "r"(b0), "r"(b1))

static __device__ __forceinline__ uint32_t cvt2(float x, float y)
{
    uint32_t r;
    asm("cvt.rn.f16x2.f32 %0, %1, %2;" : "=r"(r) : "f"(y), "f"(x));
    return r;
}

__global__ void __launch_bounds__(NTHREADS, 1)
mean_pool_hmma(const float* __restrict__ doc,
               const float* __restrict__ emap,
               const float* __restrict__ lens,
               float* __restrict__ out)
{
    extern __shared__ char smem[];
    const uint32_t sbase = smem_u32(smem);

    const int tid = threadIdx.x;
    const int wid = tid >> 5;
    const int lid = tid & 31;
    const int wm  = wid & 3;        // 4 warps in M (32 rows each)
    const int wn  = wid >> 2;       // 4 warps in N (32 cols each)

    const int b     = blockIdx.z;
    const int tileM = blockIdx.y * TILE_M;
    const int tileN = blockIdx.x * TILE_N;

    const float* A  = emap + (size_t)b * E_DIM * L_DIM + (size_t)tileM * L_DIM;
    const float* Bm = doc  + (size_t)b * L_DIM * D_DIM + tileN;
    float*       C  = out  + (size_t)b * E_DIM * D_DIM;

    float acc[2][4][4] = {};            // [m16-tile][n8-tile][frag]

    float4 araw[4];
    float4 braw[4];

    // ldmatrix lane addressing
    const uint32_t a_lrow = (uint32_t)(wm * 32 + (lid & 15));
    const uint32_t a_lcol = (uint32_t)((lid >> 4) * 16);              // bytes
    const uint32_t b_lrow = (uint32_t)(lid & 15);
    const uint32_t b_lcol = (uint32_t)(wn * 64 + (lid >> 4) * 16);    // bytes

    #define LDG_CHUNK(k0) do {                                                 \
        _Pragma("unroll")                                                      \
        for (int i = 0; i < 4; i++) {                                          \
            const int u = tid + 512 * i;                                       \
            araw[i] = *reinterpret_cast<const float4*>(                        \
                &A[(size_t)(u >> 4) * L_DIM + (k0) + (u & 15) * 4]);           \
        }                                                                      \
        _Pragma("unroll")                                                      \
        for (int i = 0; i < 4; i++) {                                          \
            const int u = tid + 512 * i;                                       \
            braw[i] = *reinterpret_cast<const float4*>(                        \
                &Bm[(size_t)((k0) + (u >> 5)) * D_DIM + (u & 31) * 4]);        \
        }                                                                      \
    } while (0)

    #define CVTSTS_CHUNK(buf) do {                                             \
        char* dstA = smem + (buf) * F16_STAGE;                                 \
        char* dstB = dstA + A16_BYTES;                                         \
        _Pragma("unroll")                                                      \
        for (int i = 0; i < 4; i++) {                                          \
            const int u = tid + 512 * i;                                       \
            float4 v = araw[i];                                                \
            *reinterpret_cast<uint2*>(dstA + (u >> 4) * A_STRIDE_B             \
                                      + (u & 15) * 8)                          \
                = make_uint2(cvt2(v.x, v.y), cvt2(v.z, v.w));                  \
        }                                                                      \
        _Pragma("unroll")                                                      \
        for (int i = 0; i < 4; i++) {                                          \
            const int u = tid + 512 * i;                                       \
            float4 v = braw[i];                                                \
            *reinterpret_cast<uint2*>(dstB + (u >> 5) * B_STRIDE_B             \
                                      + (u & 31) * 8)                          \
                = make_uint2(cvt2(v.x, v.y), cvt2(v.z, v.w));                  \
        }                                                                      \
    } while (0)

    // ---- prologue: buffers 0 and 1 filled; raw holds chunk 2 ----
    LDG_CHUNK(0);
    CVTSTS_CHUNK(0);             // DRAM stall (once)
    LDG_CHUNK(CHUNK);
    CVTSTS_CHUNK(1);             // DRAM stall (once)
    LDG_CHUNK(2 * CHUNK);        // chunk 2 in flight, full iter of slack
    __syncthreads();

    for (int c = 0; c < NCHUNK; c++) {
        // ---- compute chunk c from fp16 buffer c%4 ----
        const uint32_t f16 = sbase + (uint32_t)((c & 3) * F16_STAGE);
        const uint32_t aT  = f16;
        const uint32_t bT  = f16 + A16_BYTES;

        #pragma unroll
        for (int ko = 0; ko < 4; ko++) {            // four k16 steps
            const uint32_t akb = a_lcol + (uint32_t)(ko * 32);
            uint32_t a[2][4];
            #pragma unroll
            for (int mi = 0; mi < 2; mi++) {
                const uint32_t ao = (a_lrow + mi * 16) * A_STRIDE_B + akb;
                LDSM_X4(a[mi][0], a[mi][1], a[mi][2], a[mi][3], aT + ao);
            }
            #pragma unroll
            for (int nt = 0; nt < 2; nt++) {
                const uint32_t bo = (b_lrow + (uint32_t)(ko * 16)) * B_STRIDE_B
                                    + b_lcol + (uint32_t)(nt * 32);
                uint32_t b0, b1, b2, b3;
                LDSM_X4_T(b0, b1, b2, b3, bT + bo);
                #pragma unroll
                for (int mi = 0; mi < 2; mi++) {
                    MMA16816(acc[mi][nt * 2],     a[mi][0], a[mi][1], a[mi][2], a[mi][3], b0, b1);
                    MMA16816(acc[mi][nt * 2 + 1], a[mi][0], a[mi][1], a[mi][2], a[mi][3], b2, b3);
                }
            }
        }

        // ---- cvt+STS chunk c+2 (LDG issued at iter c-1: 1 iter of slack) ----
        if (c + 2 < NCHUNK)
            CVTSTS_CHUNK((c + 2) & 3);

        // ---- issue LDG for chunk c+3 (raw regs just freed) ----
        if (c + 3 < NCHUNK)
            LDG_CHUNK((c + 3) * CHUNK);

        // barrier every 2 chunks: write(c+2)@iter c -> read@iter c+2 has
        // >=1 barrier between; buffer reuse has >=2 (drift window = 1 chunk)
        if (c & 1)
            __syncthreads();
    }

    // ---- epilogue: scale by 1/len, store ----
    #pragma unroll
    for (int mi = 0; mi < 2; mi++) {
        const int r0 = tileM + wm * 32 + mi * 16 + (lid >> 2);
        const int r1 = r0 + 8;
        const float inv0 = 1.0f / lens[(size_t)b * E_DIM + r0];
        const float inv1 = 1.0f / lens[(size_t)b * E_DIM + r1];
        #pragma unroll
        for (int j = 0; j < 4; j++) {
            const int col = tileN + wn * 32 + j * 8 + (lid & 3) * 2;
            float2 o0 = make_float2(acc[mi][j][0] * inv0, acc[mi][j][1] * inv0);
            float2 o1 = make_float2(acc[mi][j][2] * inv1, acc[mi][j][3] * inv1);
            *reinterpret_cast<float2*>(&C[(size_t)r0 * D_DIM + col]) = o0;
            *reinterpret_cast<float2*>(&C[(size_t)r1 * D_DIM + col]) = o1;
        }
    }
}

extern "C" void kernel_launch(void* const* d_in, const int* in_sizes, int n_in,
                              void* d_out, int out_size)
{
    const float* doc  = (const float*)d_in[0];
    const float* emap = (const float*)d_in[1];
    const float* lens = (const float*)d_in[2];
    float* out = (float*)d_out;

    cudaFuncSetAttribute(mean_pool_hmma,
                         cudaFuncAttributeMaxDynamicSharedMemorySize, SMEM_TOTAL);

    dim3 grid(D_DIM / TILE_N, E_DIM / TILE_M, BATCH);   // (2, 2, 32) = 128 CTAs
    mean_pool_hmma<<<grid, NTHREADS, SMEM_TOTAL>>>(doc, emap, lens, out);
}